// round 16
// baseline (speedup 1.0000x reference)
// FSAS_V5 fused forward — persistent CTAs (grid = #SMs), one 8x8 patch per
// loop iteration, 512 threads. R16 = R15 + persistent pipeline: next-patch
// halo prefetched under phases 5-7, warm L1 across patches, g-tables hoisted,
// no wave transitions. Proj A-frags via in-loop LDG (frees regs for pipeline).
#include <cuda_runtime.h>
#include <cuda_bf16.h>
#include <cstdint>

#define HH 256
#define WW 256
#define NPATCH 4096
#define EPSF 1e-6f
#define L2T_OVER_32 0.41524101186092030f

// ---- dynamic smem layout (float offsets) ----
#define OFF_QKV  0                 // 384 * 65 fp32
#define OFF_HID  24960             // 128 * 101 fp32 hidden chunk
#define OFF_CORR OFF_HID           // 128 * 65 overlay (phase 4+)
#define OFF_G    37888             // g_norm[128], g_qnorm[128], g_knorm[128]
#define OFF_SC   38272             // sincos: cos[512], sin[512]
#define OFF_RQ   40448
#define OFF_RK   40512
#define OFF_RN   40576
#define ARENA_F  40640             // bf16 tile arena
#define XHI 0
#define XLO 14976
#define DWB 29952                  // dw weight double buffer (2 x 4608 B)
#define CBH 34816
#define CBL 52224
#define ARENA_BYTES 69632
#define SMEM_BYTES (ARENA_F * 4 + ARENA_BYTES)   // 232,192 B

// ---- prepacked weight FRAGMENTS (constant across CTAs) ----
__device__ uint32_t g_wfh[3][4096];
__device__ uint32_t g_wfl[3][4096];
__device__ uint32_t g_pfh[4096];
__device__ uint32_t g_pfl[4096];

__device__ __forceinline__ uint32_t smem_u32(const void* p) {
    uint32_t a;
    asm("{ .reg .u64 t; cvta.to.shared.u64 t, %1; cvt.u32.u64 %0, t; }"
        : "=r"(a) : "l"(p));
    return a;
}
__device__ __forceinline__ void ldsm4(uint32_t* r, uint32_t addr) {
    asm volatile("ldmatrix.sync.aligned.m8n8.x4.shared.b16 {%0,%1,%2,%3}, [%4];"
                 : "=r"(r[0]), "=r"(r[1]), "=r"(r[2]), "=r"(r[3]) : "r"(addr));
}
__device__ __forceinline__ void mma16816v(float* c, uint4 a,
                                          uint32_t b0, uint32_t b1) {
    asm volatile("mma.sync.aligned.m16n8k16.row.col.f32.bf16.bf16.f32 "
                 "{%0,%1,%2,%3}, {%4,%5,%6,%7}, {%8,%9}, {%0,%1,%2,%3};"
                 : "+f"(c[0]), "+f"(c[1]), "+f"(c[2]), "+f"(c[3])
                 : "r"(a.x), "r"(a.y), "r"(a.z), "r"(a.w), "r"(b0), "r"(b1));
}
__device__ __forceinline__ uint32_t pack_hi_lo(float v0, float v1, uint32_t& lo) {
    __nv_bfloat16 h0 = __float2bfloat16(v0);
    __nv_bfloat16 h1 = __float2bfloat16(v1);
    __nv_bfloat16 l0 = __float2bfloat16(v0 - __bfloat162float(h0));
    __nv_bfloat16 l1 = __float2bfloat16(v1 - __bfloat162float(h1));
    lo = ((uint32_t)__bfloat16_as_ushort(l1) << 16) | __bfloat16_as_ushort(l0);
    return ((uint32_t)__bfloat16_as_ushort(h1) << 16) | __bfloat16_as_ushort(h0);
}
__device__ __forceinline__ uint64_t pk2(float lo, float hi) {
    uint64_t r; asm("mov.b64 %0, {%1, %2};" : "=l"(r) : "f"(lo), "f"(hi)); return r;
}
__device__ __forceinline__ void upk2(float& lo, float& hi, uint64_t v) {
    asm("mov.b64 {%0, %1}, %2;" : "=f"(lo), "=f"(hi) : "l"(v));
}
__device__ __forceinline__ void fma2(uint64_t& d, uint64_t a, uint64_t b) {
    asm("fma.rn.f32x2 %0, %1, %2, %0;" : "+l"(d) : "l"(a), "l"(b));
}

// circ conv body, i-parity P compile-time (see R9).
template<int P>
__device__ __forceinline__ void circ_par(const float* qb, const float* kb,
                                         int A0, float* outv)
{
    uint64_t krp[4][8];
    #pragma unroll
    for (int t = 0; t < 4; ++t) {
        #pragma unroll
        for (int c = 0; c < 8; ++c) {
            int r0 = (2*t + P + A0) & 7;
            int r1 = (2*t + P + 1 + A0) & 7;
            krp[t][c] = pk2(kb[r0*8 + c], kb[r1*8 + c]);
        }
    }
    uint64_t acc2[2][8];
    #pragma unroll
    for (int rp = 0; rp < 2; ++rp)
        #pragma unroll
        for (int bb = 0; bb < 8; ++bb) acc2[rp][bb] = pk2(0.f, 0.f);
    #pragma unroll
    for (int ii = 0; ii < 4; ++ii) {
        const int i = P + 2*ii;
        #pragma unroll
        for (int j = 0; j < 8; ++j) {
            float qs = qb[i*8 + j];
            uint64_t qq = pk2(qs, qs);
            #pragma unroll
            for (int rp = 0; rp < 2; ++rp) {
                const int t = (rp - P - ii) & 3;
                #pragma unroll
                for (int bb = 0; bb < 8; ++bb)
                    fma2(acc2[rp][bb], qq, krp[t][(bb - j) & 7]);
            }
        }
    }
    #pragma unroll
    for (int rp = 0; rp < 2; ++rp)
        #pragma unroll
        for (int bb = 0; bb < 8; ++bb)
            upk2(outv[(2*rp)*8 + bb], outv[(2*rp+1)*8 + bb], acc2[rp][bb]);
}

// halo prefetch: load + bf16-split-pack 7 items/thread into registers
__device__ __forceinline__ void halo_pref(const float* __restrict__ x, int p,
                                          int warp, int lane,
                                          uint32_t* hq, uint32_t* lq)
{
    int px = p & 31, py = (p >> 5) & 31, b = p >> 10;
    int gx0 = px * 8, gy0 = py * 8;
    const float* xb = x + (size_t)b * 64 * HH * WW;
    #pragma unroll
    for (int t = 0; t < 7; ++t) {
        int it = warp + 16 * t;
        float x0 = 0.f, x1 = 0.f;
        if (it < 104) {
            int cpBase = it / 13;
            int posBase = it - cpBase * 13;
            int cp  = cpBase * 4 + (lane >> 3);
            int pos = posBase * 8 + (lane & 7);
            if (pos < 100) {
                int Y = pos / 10, X = pos - Y * 10;
                int gy = gy0 - 1 + Y, gx = gx0 - 1 + X;
                if ((unsigned)gy < HH && (unsigned)gx < WW) {
                    size_t base = (size_t)(2 * cp) * (HH * WW) + gy * WW + gx;
                    x0 = __ldg(xb + base);
                    x1 = __ldg(xb + base + (size_t)(HH * WW));
                }
            }
        }
        hq[t] = pack_hi_lo(x0, x1, lq[t]);
    }
}

// ---- prep kernel: pack weights into mma A-fragment layout ----
__global__ void prep_weights(const float* __restrict__ w_hidden,
                             const float* __restrict__ w_proj)
{
    int t = blockIdx.x * blockDim.x + threadIdx.x;
    if (t < 3072) {
        int c = t >> 10, s = t & 1023;
        int lane = s & 31, ks = (s >> 5) & 3, mt = (s >> 7) & 1, mg = s >> 8;
        #pragma unroll
        for (int r = 0; r < 4; ++r) {
            int row = c * 128 + mg * 32 + mt * 16 + (r & 1) * 8 + (lane >> 2);
            int col = ks * 16 + ((r >> 1) & 1) * 8 + (lane & 3) * 2;
            float v0 = w_hidden[row * 64 + col];
            float v1 = w_hidden[row * 64 + col + 1];
            uint32_t lp, hp = pack_hi_lo(v0, v1, lp);
            g_wfh[c][s * 4 + r] = hp;
            g_wfl[c][s * 4 + r] = lp;
        }
    } else if (t < 4096) {
        int s = t - 3072;
        int lane = s & 31, ks = (s >> 5) & 7, mg = s >> 8;
        #pragma unroll
        for (int r = 0; r < 4; ++r) {
            int row = mg * 16 + (r & 1) * 8 + (lane >> 2);
            int col = ks * 16 + ((r >> 1) & 1) * 8 + (lane & 3) * 2;
            float v0 = w_proj[row * 128 + col];
            float v1 = w_proj[row * 128 + col + 1];
            uint32_t lp, hp = pack_hi_lo(v0, v1, lp);
            g_pfh[s * 4 + r] = hp;
            g_pfl[s * 4 + r] = lp;
        }
    }
}

__global__ __launch_bounds__(512, 1)
void fsas_fused_kernel(const float* __restrict__ x,
                       const float* __restrict__ w_dw,
                       const float* __restrict__ g_norm,
                       const float* __restrict__ g_qnorm,
                       const float* __restrict__ g_knorm,
                       float* __restrict__ out)
{
    extern __shared__ float sm[];
    const int tid  = threadIdx.x;
    const int lane = tid & 31;
    const int warp = tid >> 5;
    char* smc = (char*)sm;
    const uint32_t sbase = smem_u32(sm);
    const uint32_t arena = sbase + ARENA_F * 4;
    const int mg = warp & 3;

    // ---- hoisted: g tables (constant across patches) ----
    if (tid < 384) {
        float v = (tid < 128) ? __ldg(g_norm + tid)
                : (tid < 256) ? __ldg(g_qnorm + tid - 128)
                              : __ldg(g_knorm + tid - 256);
        sm[OFF_G + tid] = v;
    }
    // dw chunk 0 -> regs
    float dwpre[3];
    #pragma unroll
    for (int t = 0; t < 3; ++t) {
        int idx = tid + t * 512;
        dwpre[t] = (idx < 1152) ? __ldg(w_dw + idx) : 0.f;
    }
    // halo for first patch
    int p = blockIdx.x;
    uint32_t hq[7], lq[7];
    if (p < NPATCH) halo_pref(x, p, warp, lane, hq, lq);

    while (p < NPATCH) {
        const int px = p & 31, py = (p >> 5) & 31, b = p >> 10;
        const int gx0 = px * 8, gy0 = py * 8;

        // ---- loop top: STS halo (prefetched), sincos, dw buf0, A-frags c0 ----
        #pragma unroll
        for (int t = 0; t < 7; ++t) {
            int it = warp + 16 * t;
            if (it < 104) {
                int cpBase = it / 13;
                int posBase = it - cpBase * 13;
                int cp  = cpBase * 4 + (lane >> 3);
                int pos = posBase * 8 + (lane & 7);
                uint32_t off = (uint32_t)(pos * 144 + cp * 4);
                *(uint32_t*)(smc + ARENA_F * 4 + XHI + off) = hq[t];
                *(uint32_t*)(smc + ARENA_F * 4 + XLO + off) = lq[t];
            }
        }
        {   // sincos table (per patch)
            int flag = tid >> 8, mm = (tid >> 3) & 31, d = tid & 7;
            float pos = (float)((flag ? gx0 : gy0) + d);
            float inv = exp2f(-L2T_OVER_32 * (float)mm);
            float sn, cs;
            sincosf(pos * inv, &sn, &cs);
            sm[OFF_SC + flag * 256 + mm * 8 + d]       = cs;
            sm[OFF_SC + 512 + flag * 256 + mm * 8 + d] = sn;
        }
        {   // dw chunk 0 -> buffer 0
            float* dwb0 = (float*)(smc + ARENA_F * 4 + DWB);
            #pragma unroll
            for (int t = 0; t < 3; ++t) {
                int idx = tid + t * 512;
                if (idx < 1152) dwb0[idx] = dwpre[t];
            }
        }
        // prefetch dw chunk 1
        #pragma unroll
        for (int t = 0; t < 3; ++t) {
            int idx = tid + t * 512;
            dwpre[t] = (idx < 1152) ? __ldg(w_dw + 1152 + idx) : 0.f;
        }
        // A-frags chunk 0 (warm L1 after first patch)
        uint4 afh[2][4], afl[2][4];
        #pragma unroll
        for (int mt = 0; mt < 2; ++mt)
            #pragma unroll
            for (int ks = 0; ks < 4; ++ks) {
                int slot = ((mg * 2 + mt) * 4 + ks) * 32 + lane;
                afh[mt][ks] = *(const uint4*)&g_wfh[0][slot * 4];
                afl[mt][ks] = *(const uint4*)&g_wfl[0][slot * 4];
            }
        __syncthreads();

        // ============ phase 1: expand (HMMA, A from regs) + depthwise ============
        for (int c = 0; c < 3; ++c) {
            {
                const int ng = warp >> 2;
                const int nt0 = (ng == 0) ? 0 : 3 * ng + 1;
                const int cnt = (ng == 0) ? 4 : 3;
                for (int t = 0; t < cnt; ++t) {
                    int nt = nt0 + t;
                    float acc[2][4] = {};
                    const uint32_t bB = arena + XHI + (lane >> 4) * (XLO - XHI)
                                        + (nt * 8 + (lane & 7)) * 144
                                        + ((lane >> 3) & 1) * 16;
                    #pragma unroll
                    for (int ks = 0; ks < 4; ++ks) {
                        uint32_t bf[4];
                        ldsm4(bf, bB + ks * 32);
                        #pragma unroll
                        for (int mt = 0; mt < 2; ++mt) {
                            mma16816v(acc[mt], afh[mt][ks], bf[0], bf[1]);
                            mma16816v(acc[mt], afh[mt][ks], bf[2], bf[3]);
                            mma16816v(acc[mt], afl[mt][ks], bf[0], bf[1]);
                        }
                    }
                    int pp = nt * 8 + 2 * (lane & 3);
                    #pragma unroll
                    for (int mt = 0; mt < 2; ++mt) {
                        int o = mg * 32 + mt * 16 + (lane >> 2);
                        if (pp < 100) {
                            sm[OFF_HID + o * 101 + pp]       = acc[mt][0];
                            sm[OFF_HID + (o + 8) * 101 + pp] = acc[mt][2];
                        }
                        if (pp + 1 < 100) {
                            sm[OFF_HID + o * 101 + pp + 1]       = acc[mt][1];
                            sm[OFF_HID + (o + 8) * 101 + pp + 1] = acc[mt][3];
                        }
                    }
                }
            }
            __syncthreads();   // HID ready; A-frag regs dead

            if (c < 2) {
                #pragma unroll
                for (int mt = 0; mt < 2; ++mt)
                    #pragma unroll
                    for (int ks = 0; ks < 4; ++ks) {
                        int slot = ((mg * 2 + mt) * 4 + ks) * 32 + lane;
                        afh[mt][ks] = *(const uint4*)&g_wfh[c + 1][slot * 4];
                        afl[mt][ks] = *(const uint4*)&g_wfl[c + 1][slot * 4];
                    }
                float* dwbn = (float*)(smc + ARENA_F * 4 + DWB + ((c + 1) & 1) * 4608);
                #pragma unroll
                for (int t = 0; t < 3; ++t) {
                    int idx = tid + t * 512;
                    if (idx < 1152) dwbn[idx] = dwpre[t];
                }
                if (c < 1) {
                    #pragma unroll
                    for (int t = 0; t < 3; ++t) {
                        int idx = tid + t * 512;
                        dwpre[t] = (idx < 1152) ? __ldg(w_dw + 2 * 1152 + idx) : 0.f;
                    }
                }
            }

            // depthwise 3x3 (f32x2)
            {
                int ch = tid & 127, g = tid >> 7;
                const float* wd = (const float*)(smc + ARENA_F * 4 + DWB
                                                 + (c & 1) * 4608) + ch * 9;
                uint64_t ww[9];
                #pragma unroll
                for (int t = 0; t < 9; ++t) { float w = wd[t]; ww[t] = pk2(w, w); }
                const float* hb = &sm[OFF_HID + ch * 101 + 2 * g];
                uint64_t Ap[3], Bp[3], Cp[3];
                {
                    float a0 = hb[0], a1 = hb[1], a2 = hb[2], a3 = hb[3];
                    Ap[0] = pk2(a0, a1); Ap[1] = pk2(a1, a2); Ap[2] = pk2(a2, a3);
                    float b0 = hb[10], b1 = hb[11], b2 = hb[12], b3 = hb[13];
                    Bp[0] = pk2(b0, b1); Bp[1] = pk2(b1, b2); Bp[2] = pk2(b2, b3);
                }
                float* qrow = &sm[OFF_QKV + (c * 128 + ch) * 65 + 2 * g];
                #pragma unroll
                for (int r = 2; r < 10; ++r) {
                    float c0 = hb[r*10+0], c1 = hb[r*10+1], c2 = hb[r*10+2], c3 = hb[r*10+3];
                    Cp[0] = pk2(c0, c1); Cp[1] = pk2(c1, c2); Cp[2] = pk2(c2, c3);
                    uint64_t s2 = pk2(0.f, 0.f);
                    fma2(s2, ww[0], Ap[0]); fma2(s2, ww[1], Ap[1]); fma2(s2, ww[2], Ap[2]);
                    fma2(s2, ww[3], Bp[0]); fma2(s2, ww[4], Bp[1]); fma2(s2, ww[5], Bp[2]);
                    fma2(s2, ww[6], Cp[0]); fma2(s2, ww[7], Cp[1]); fma2(s2, ww[8], Cp[2]);
                    float o0, o1; upk2(o0, o1, s2);
                    int yy = r - 2;
                    qrow[yy * 8 + 0] = o0; qrow[yy * 8 + 1] = o1;
                    Ap[0]=Bp[0]; Ap[1]=Bp[1]; Ap[2]=Bp[2];
                    Bp[0]=Cp[0]; Bp[1]=Cp[1]; Bp[2]=Cp[2];
                }
            }
            if (c < 2) __syncthreads();
        }

        // ---- phase 2: RMS factors for q and k (warp -> 4 pixels) ----
        #pragma unroll
        for (int pi = 0; pi < 4; ++pi) {
            int pix = warp * 4 + pi;
            float sq = 0.f, sk = 0.f;
            #pragma unroll
            for (int r = 0; r < 4; ++r) {
                int cc = lane + r * 32;
                float qv = sm[OFF_QKV + cc * 65 + pix];
                float kv = sm[OFF_QKV + (128 + cc) * 65 + pix];
                sq = fmaf(qv, qv, sq);
                sk = fmaf(kv, kv, sk);
            }
            #pragma unroll
            for (int off = 16; off; off >>= 1) {
                sq += __shfl_xor_sync(0xffffffffu, sq, off);
                sk += __shfl_xor_sync(0xffffffffu, sk, off);
            }
            if (lane == 0) {
                sm[OFF_RQ + pix] = rsqrtf(sq * (1.f / 128.f) + EPSF);
                sm[OFF_RK + pix] = rsqrtf(sk * (1.f / 128.f) + EPSF);
            }
        }
        __syncthreads();

        // ---- phase 3: RMSNorm scale + 2D RoPE (table-driven) ----
        for (int idx = tid; idx < 64 * 64; idx += 512) {
            int m = idx >> 6, pix = idx & 63;
            int flag = (m >> 5), mm = m & 31;
            int d = flag ? (pix & 7) : (pix >> 3);
            float cs = sm[OFF_SC + flag * 256 + mm * 8 + d];
            float sn = sm[OFF_SC + 512 + flag * 256 + mm * 8 + d];
            int c0 = 2 * m;
            float rqp = sm[OFF_RQ + pix], rkp = sm[OFF_RK + pix];
            float gq0 = sm[OFF_G + 128 + c0], gq1 = sm[OFF_G + 129 + c0];
            float gk0 = sm[OFF_G + 256 + c0], gk1 = sm[OFF_G + 257 + c0];

            float q0 = sm[OFF_QKV + c0 * 65 + pix]       * rqp * gq0;
            float q1 = sm[OFF_QKV + (c0 + 1) * 65 + pix] * rqp * gq1;
            sm[OFF_QKV + c0 * 65 + pix]       = q0 * cs - q1 * sn;
            sm[OFF_QKV + (c0 + 1) * 65 + pix] = q1 * cs + q0 * sn;

            float k0 = sm[OFF_QKV + (128 + c0) * 65 + pix] * rkp * gk0;
            float k1 = sm[OFF_QKV + (129 + c0) * 65 + pix] * rkp * gk1;
            sm[OFF_QKV + (128 + c0) * 65 + pix] = k0 * cs - k1 * sn;
            sm[OFF_QKV + (129 + c0) * 65 + pix] = k1 * cs + k0 * sn;
        }
        __syncthreads();

        // ---- phase 4: circ conv, f32x2 parity-split ----
        {
            const int cc = tid & 127;
            const int A0 = ((tid >> 7) & 1) * 4;
            const int P  = tid >> 8;
            const float* qb = &sm[OFF_QKV + cc * 65];
            const float* kb = &sm[OFF_QKV + (128 + cc) * 65];
            float v32[32];
            if (P == 0) circ_par<0>(qb, kb, A0, v32);
            else        circ_par<1>(qb, kb, A0, v32);

            float* scratch = (float*)(smc + ARENA_F * 4 + CBH);
            int s = tid & 255;
            if (P == 1) {
                #pragma unroll
                for (int t = 0; t < 32; ++t) scratch[s * 33 + t] = v32[t];
            }
            __syncthreads();
            if (P == 0) {
                #pragma unroll
                for (int t = 0; t < 32; ++t) {
                    float tot = v32[t] + scratch[s * 33 + t];
                    sm[OFF_CORR + cc * 65 + (A0 + (t >> 3)) * 8 + (t & 7)] = tot;
                }
            }
        }
        __syncthreads();

        // ---- prefetch next patch's halo (hidden under phases 5-7) ----
        const int pn = p + gridDim.x;
        if (pn < NPATCH) halo_pref(x, pn, warp, lane, hq, lq);

        // ---- phase 5: corr RMS factor (warp -> 4 pixels) ----
        #pragma unroll
        for (int pi = 0; pi < 4; ++pi) {
            int pix = warp * 4 + pi;
            float sc = 0.f;
            #pragma unroll
            for (int r = 0; r < 4; ++r) {
                float cv = sm[OFF_CORR + (lane + r * 32) * 65 + pix];
                sc = fmaf(cv, cv, sc);
            }
            #pragma unroll
            for (int off = 16; off; off >>= 1)
                sc += __shfl_xor_sync(0xffffffffu, sc, off);
            if (lane == 0)
                sm[OFF_RN + pix] = rsqrtf(sc * (1.f / 128.f) + EPSF);
        }
        __syncthreads();

        // ---- phase 6: (v * g_norm * rn * corr) -> bf16 hi/lo B tiles ----
        for (int idx = tid; idx < 64 * 64; idx += 512) {
            int pix = idx >> 6, kp = idx & 63;
            int k0 = 2 * kp;
            float rnp = sm[OFF_RN + pix];
            float c0v = sm[OFF_CORR + k0 * 65 + pix];
            float c1v = sm[OFF_CORR + (k0 + 1) * 65 + pix];
            float v0  = sm[OFF_QKV + (256 + k0) * 65 + pix];
            float v1  = sm[OFF_QKV + (257 + k0) * 65 + pix];
            float w0 = v0 * c0v * rnp * sm[OFF_G + k0];
            float w1 = v1 * c1v * rnp * sm[OFF_G + k0 + 1];
            uint32_t lp, hp = pack_hi_lo(w0, w1, lp);
            *(uint32_t*)(smc + ARENA_F * 4 + CBH + pix * 272 + kp * 4) = hp;
            *(uint32_t*)(smc + ARENA_F * 4 + CBL + pix * 272 + kp * 4) = lp;
        }
        __syncthreads();

        // ---- phase 7: projection HMMA, A via in-loop LDG (warm L1) ----
        {
            const int nh = warp >> 2;
            float* ob = out + (size_t)b * 64 * HH * WW;
            float acc[2][4] = {};
            #pragma unroll
            for (int ks = 0; ks < 8; ++ks) {
                int slot = (mg * 8 + ks) * 32 + lane;
                uint4 pfh = *(const uint4*)&g_pfh[slot * 4];
                uint4 pfl = *(const uint4*)&g_pfl[slot * 4];
                #pragma unroll
                for (int t = 0; t < 2; ++t) {
                    int nt = nh * 2 + t;
                    const uint32_t bB = arena + CBH + (lane >> 4) * (CBL - CBH)
                                        + (nt * 8 + (lane & 7)) * 272
                                        + ((lane >> 3) & 1) * 16 + ks * 32;
                    uint32_t bf[4];
                    ldsm4(bf, bB);
                    mma16816v(acc[t], pfh, bf[0], bf[1]);
                    mma16816v(acc[t], pfh, bf[2], bf[3]);
                    mma16816v(acc[t], pfl, bf[0], bf[1]);
                }
            }
            #pragma unroll
            for (int t = 0; t < 2; ++t) {
                int nt = nh * 2 + t;
                int o = mg * 16 + (lane >> 2);
                int gy = gy0 + nt;
                int gxp = gx0 + 2 * (lane & 3);
                *(float2*)(ob + (size_t)o * (HH * WW) + gy * WW + gxp)
                    = make_float2(acc[t][0], acc[t][1]);
                *(float2*)(ob + (size_t)(o + 8) * (HH * WW) + gy * WW + gxp)
                    = make_float2(acc[t][2], acc[t][3]);
            }
        }

        // ---- loop bottom: re-prefetch dw chunk 0 for next patch ----
        #pragma unroll
        for (int t = 0; t < 3; ++t) {
            int idx = tid + t * 512;
            dwpre[t] = (idx < 1152) ? __ldg(w_dw + idx) : 0.f;
        }
        p = pn;
    }
}

extern "C" void kernel_launch(void* const* d_in, const int* in_sizes, int n_in,
                              void* d_out, int out_size)
{
    (void)in_sizes; (void)n_in; (void)out_size;
    const float* x        = (const float*)d_in[0];
    const float* w_hidden = (const float*)d_in[1];
    const float* w_dw     = (const float*)d_in[2];
    const float* w_proj   = (const float*)d_in[3];
    const float* g_norm   = (const float*)d_in[4];
    const float* g_qnorm  = (const float*)d_in[5];
    const float* g_knorm  = (const float*)d_in[6];
    float* out = (float*)d_out;

    prep_weights<<<16, 256>>>(w_hidden, w_proj);

    int dev = 0, sms = 0;
    cudaGetDevice(&dev);
    cudaDeviceGetAttribute(&sms, cudaDevAttrMultiProcessorCount, dev);
    if (sms <= 0) sms = 148;
    if (sms > NPATCH) sms = NPATCH;

    cudaFuncSetAttribute(fsas_fused_kernel,
                         cudaFuncAttributeMaxDynamicSharedMemorySize, SMEM_BYTES);
    fsas_fused_kernel<<<sms, 512, SMEM_BYTES>>>(
        x, w_dw, g_norm, g_qnorm, g_knorm, out);
}